// round 3
// baseline (speedup 1.0000x reference)
#include <cuda_runtime.h>
#include <math_constants.h>

// Hausdorff loss: x,y (8, 4096, 3) fp32 -> scalar.
// loss_n = max( max_j min_i d(x_i,y_j), max_i min_j d(x_i,y_j) )
//        = max over all per-point nearest-neighbor distances (both directions).
// Work on squared distances; sqrt once per batch at the end.

#define NB 8        // batches
#define V 4096      // points per cloud
#define TS 2048     // target tile in smem (float4 = 32KB)
#define THREADS 256
#define QPB 512     // queries per block (2 per thread)
#define CHUNKS (V / QPB)   // 8

__device__ unsigned g_max[NB];

__global__ void hd_init_kernel() {
    if (threadIdx.x < NB) g_max[threadIdx.x] = 0u;
}

__global__ void __launch_bounds__(THREADS, 1)
hd_main_kernel(const float* __restrict__ X, const float* __restrict__ Y) {
    __shared__ float4 sT[TS];
    __shared__ float wmax[THREADS / 32];

    const int b   = blockIdx.y;
    const int dir = blockIdx.z;
    const float* __restrict__ Qp = (dir == 0 ? X : Y) + (size_t)b * V * 3;
    const float* __restrict__ Tp = (dir == 0 ? Y : X) + (size_t)b * V * 3;

    const int tid = threadIdx.x;
    const int q0 = blockIdx.x * QPB + tid;
    const int q1 = q0 + THREADS;

    // Load this thread's two query points; precompute -2*q and |q|^2.
    const float q0x = Qp[q0 * 3 + 0], q0y = Qp[q0 * 3 + 1], q0z = Qp[q0 * 3 + 2];
    const float q1x = Qp[q1 * 3 + 0], q1y = Qp[q1 * 3 + 1], q1z = Qp[q1 * 3 + 2];
    const float a0x = -2.0f * q0x, a0y = -2.0f * q0y, a0z = -2.0f * q0z;
    const float a1x = -2.0f * q1x, a1y = -2.0f * q1y, a1z = -2.0f * q1z;
    const float q2_0 = q0x * q0x + q0y * q0y + q0z * q0z;
    const float q2_1 = q1x * q1x + q1y * q1y + q1z * q1z;

    float m0 = CUDART_INF_F;
    float m1 = CUDART_INF_F;

    #pragma unroll
    for (int t = 0; t < V / TS; t++) {
        __syncthreads();
        // Cooperative load of TS target points as (x,y,z,|t|^2).
        for (int i = tid; i < TS; i += THREADS) {
            const int g = t * TS + i;
            const float tx = Tp[g * 3 + 0];
            const float ty = Tp[g * 3 + 1];
            const float tz = Tp[g * 3 + 2];
            sT[i] = make_float4(tx, ty, tz, tx * tx + ty * ty + tz * tz);
        }
        __syncthreads();

        #pragma unroll 8
        for (int j = 0; j < TS; j++) {
            const float4 p = sT[j];   // broadcast LDS.128
            // v = |t|^2 - 2 q.t   (add |q|^2 after the min)
            const float v0 = fmaf(a0x, p.x, fmaf(a0y, p.y, fmaf(a0z, p.z, p.w)));
            const float v1 = fmaf(a1x, p.x, fmaf(a1y, p.y, fmaf(a1z, p.z, p.w)));
            m0 = fminf(m0, v0);
            m1 = fminf(m1, v1);
        }
    }

    // Per-thread max of squared NN distances for its two queries.
    const float s0 = fmaxf(q2_0 + m0, 0.0f);
    const float s1 = fmaxf(q2_1 + m1, 0.0f);
    float m = fmaxf(s0, s1);

    // Warp max-reduce.
    #pragma unroll
    for (int off = 16; off > 0; off >>= 1)
        m = fmaxf(m, __shfl_xor_sync(0xffffffffu, m, off));
    if ((tid & 31) == 0) wmax[tid >> 5] = m;
    __syncthreads();

    if (tid == 0) {
        float mm = wmax[0];
        #pragma unroll
        for (int w = 1; w < THREADS / 32; w++) mm = fmaxf(mm, wmax[w]);
        // Nonnegative floats: uint bit-pattern ordering == float ordering.
        atomicMax(&g_max[b], __float_as_uint(mm));
    }
}

__global__ void hd_final_kernel(float* __restrict__ out) {
    if (threadIdx.x == 0) {
        float s = 0.0f;
        #pragma unroll
        for (int i = 0; i < NB; i++) s += sqrtf(__uint_as_float(g_max[i]));
        out[0] = s * (1.0f / (float)NB);   // LOSS_WEIGHT = 1.0
    }
}

extern "C" void kernel_launch(void* const* d_in, const int* in_sizes, int n_in,
                              void* d_out, int out_size) {
    const float* x = (const float*)d_in[0];
    const float* y = (const float*)d_in[1];
    float* out = (float*)d_out;

    hd_init_kernel<<<1, 32>>>();
    dim3 grid(CHUNKS, NB, 2);
    hd_main_kernel<<<grid, THREADS>>>(x, y);
    hd_final_kernel<<<1, 32>>>(out);
}